// round 1
// baseline (speedup 1.0000x reference)
#include <cuda_runtime.h>
#include <cstdint>

// LSTM: B=4096, T=256, I=8, H=32, O=1.
// One warp processes 4 batch elements; lane j owns hidden unit j (all 4 gates).
// Gates packed as f32x2 pairs {i,f},{g,o}; recurrent weights in shared as
// float4 [k][j][gate] so LDS.128 gives both weight pairs directly.
// h double-buffered in shared, broadcast-read (16B) per k.
// CTA = 128 threads (4 warps, 16 batches). Grid = 256.

#define B_TOT 4096
#define T_TOT 256
#define I_SZ 8
#define H_SZ 32
#define WARPS_PER_CTA 4
#define NB 4                      // batches per warp
#define BATCH_PER_CTA (WARPS_PER_CTA * NB)
#define CHUNK 16                  // time steps staged per x-chunk

typedef unsigned long long u64;

__device__ __forceinline__ u64 pack2(float a, float b) {
    u64 r; asm("mov.b64 %0,{%1,%2};" : "=l"(r) : "f"(a), "f"(b)); return r;
}
__device__ __forceinline__ void unpack2(u64 v, float& a, float& b) {
    asm("mov.b64 {%0,%1},%2;" : "=f"(a), "=f"(b) : "l"(v));
}
__device__ __forceinline__ u64 fma2(u64 a, u64 b, u64 c) {
    u64 d; asm("fma.rn.f32x2 %0,%1,%2,%3;" : "=l"(d) : "l"(a), "l"(b), "l"(c)); return d;
}

__device__ __forceinline__ float fsigmoid(float z) {
    // 1/(1+exp(-z)); exp via EX2, div via RCP. Saturates correctly at +-inf.
    return __fdividef(1.0f, 1.0f + __expf(-z));
}
__device__ __forceinline__ float ftanh_(float z) {
    // tanh(x) = 1 - 2/(exp(2x)+1); NaN-free at both extremes.
    return 1.0f - __fdividef(2.0f, __expf(2.0f * z) + 1.0f);
}

// Shared layout sizes (in floats)
#define WH_WORDS (32 * 32 * 4)            // [k][j][g] float  -> float4 per (k,j)
#define WI_WORDS (8 * 32 * 4)             // [i][j][g]
#define X_T_STRIDE 164                    // 8*20 + 4 pad: breaks bank periodicity
#define X_I_STRIDE 20                     // 16 batches + 4 pad
#define X_WORDS (CHUNK * X_T_STRIDE)
#define H_K_STRIDE 20                     // 16 batches + 4 pad
#define H_BUF_WORDS (32 * H_K_STRIDE)

__global__ void __launch_bounds__(128, 2)
lstm_kernel(const float* __restrict__ x,
            const float* __restrict__ W_ih,
            const float* __restrict__ W_hh,
            const float* __restrict__ b_ih,
            const float* __restrict__ b_hh,
            const float* __restrict__ W_out,
            const float* __restrict__ b_out,
            float* __restrict__ out)
{
    __shared__ __align__(16) float Wh_sm[WH_WORDS];
    __shared__ __align__(16) float Wi_sm[WI_WORDS];
    __shared__ __align__(16) float x_sm[X_WORDS];
    __shared__ __align__(16) float h_sm[2 * H_BUF_WORDS];

    const int tid  = threadIdx.x;
    const int lane = tid & 31;
    const int warp = tid >> 5;
    const int warp4 = warp * NB;

    // ---- stage weights: Wh_sm[(k*32+j)*4 + g] = W_hh[(g*32+j)*32 + k] ----
    for (int idx = tid; idx < 128 * 32; idx += 128) {
        int row = idx >> 5;           // g*32+j
        int k   = idx & 31;
        int g   = row >> 5;
        int j   = row & 31;
        Wh_sm[(k * 32 + j) * 4 + g] = W_hh[idx];
    }
    for (int idx = tid; idx < 128 * 8; idx += 128) {
        int row = idx >> 3;
        int i   = idx & 7;
        int g   = row >> 5;
        int j   = row & 31;
        Wi_sm[(i * 32 + j) * 4 + g] = W_ih[idx];
    }
    for (int idx = tid; idx < 2 * H_BUF_WORDS; idx += 128) h_sm[idx] = 0.0f;

    // per-lane combined bias, packed as gate pairs
    const float bi = b_ih[0 * 32 + lane] + b_hh[0 * 32 + lane];
    const float bf = b_ih[1 * 32 + lane] + b_hh[1 * 32 + lane];
    const float bg = b_ih[2 * 32 + lane] + b_hh[2 * 32 + lane];
    const float bo = b_ih[3 * 32 + lane] + b_hh[3 * 32 + lane];
    const u64 bias_if = pack2(bi, bf);
    const u64 bias_go = pack2(bg, bo);

    float c0 = 0.f, c1 = 0.f, c2 = 0.f, c3 = 0.f;
    float hl0 = 0.f, hl1 = 0.f, hl2 = 0.f, hl3 = 0.f;

    int cur = 0;

    const size_t xbase = (size_t)blockIdx.x * BATCH_PER_CTA * T_TOT * I_SZ;

#pragma unroll 1
    for (int tc = 0; tc < T_TOT / CHUNK; ++tc) {
        __syncthreads();   // everyone done with previous x chunk
        // ---- stage x chunk: x_sm[t][i][b] (padded) ----
#pragma unroll
        for (int q = 0; q < 4; ++q) {
            int b = q * 4 + warp;                 // 0..15
            int t = lane >> 1;                    // 0..15
            int i0 = (lane & 1) * 4;              // 0 or 4
            const float4 v = *(const float4*)(x + xbase
                              + ((size_t)b * T_TOT + tc * CHUNK + t) * I_SZ + i0);
            float* dst = x_sm + t * X_T_STRIDE + i0 * X_I_STRIDE + b;
            dst[0 * X_I_STRIDE] = v.x;
            dst[1 * X_I_STRIDE] = v.y;
            dst[2 * X_I_STRIDE] = v.z;
            dst[3 * X_I_STRIDE] = v.w;
        }
        __syncthreads();

#pragma unroll 1
        for (int s = 0; s < CHUNK; ++s) {
            const float* hr = h_sm + cur * H_BUF_WORDS;
            float*       hw = h_sm + (cur ^ 1) * H_BUF_WORDS;

            u64 zif0 = bias_if, zif1 = bias_if, zif2 = bias_if, zif3 = bias_if;
            u64 zgo0 = bias_go, zgo1 = bias_go, zgo2 = bias_go, zgo3 = bias_go;

            // ---- input projection ----
#pragma unroll
            for (int i = 0; i < I_SZ; ++i) {
                const float4 xv = *(const float4*)(x_sm + s * X_T_STRIDE + i * X_I_STRIDE + warp4);
                const ulonglong2 wv = *(const ulonglong2*)(Wi_sm + (i * 32 + lane) * 4);
                const u64 d0 = pack2(xv.x, xv.x);
                const u64 d1 = pack2(xv.y, xv.y);
                const u64 d2 = pack2(xv.z, xv.z);
                const u64 d3 = pack2(xv.w, xv.w);
                zif0 = fma2(d0, wv.x, zif0); zgo0 = fma2(d0, wv.y, zgo0);
                zif1 = fma2(d1, wv.x, zif1); zgo1 = fma2(d1, wv.y, zgo1);
                zif2 = fma2(d2, wv.x, zif2); zgo2 = fma2(d2, wv.y, zgo2);
                zif3 = fma2(d3, wv.x, zif3); zgo3 = fma2(d3, wv.y, zgo3);
            }

            // ---- recurrent projection ----
#pragma unroll
            for (int k = 0; k < H_SZ; ++k) {
                const float4 hv = *(const float4*)(hr + k * H_K_STRIDE + warp4);
                const ulonglong2 wv = *(const ulonglong2*)(Wh_sm + (k * 32 + lane) * 4);
                const u64 d0 = pack2(hv.x, hv.x);
                const u64 d1 = pack2(hv.y, hv.y);
                const u64 d2 = pack2(hv.z, hv.z);
                const u64 d3 = pack2(hv.w, hv.w);
                zif0 = fma2(d0, wv.x, zif0); zgo0 = fma2(d0, wv.y, zgo0);
                zif1 = fma2(d1, wv.x, zif1); zgo1 = fma2(d1, wv.y, zgo1);
                zif2 = fma2(d2, wv.x, zif2); zgo2 = fma2(d2, wv.y, zgo2);
                zif3 = fma2(d3, wv.x, zif3); zgo3 = fma2(d3, wv.y, zgo3);
            }

            // ---- gates, state update ----
            float zi, zf, zg, zo;
            unpack2(zif0, zi, zf); unpack2(zgo0, zg, zo);
            c0 = fsigmoid(zf) * c0 + fsigmoid(zi) * ftanh_(zg);
            hl0 = fsigmoid(zo) * ftanh_(c0);

            unpack2(zif1, zi, zf); unpack2(zgo1, zg, zo);
            c1 = fsigmoid(zf) * c1 + fsigmoid(zi) * ftanh_(zg);
            hl1 = fsigmoid(zo) * ftanh_(c1);

            unpack2(zif2, zi, zf); unpack2(zgo2, zg, zo);
            c2 = fsigmoid(zf) * c2 + fsigmoid(zi) * ftanh_(zg);
            hl2 = fsigmoid(zo) * ftanh_(c2);

            unpack2(zif3, zi, zf); unpack2(zgo3, zg, zo);
            c3 = fsigmoid(zf) * c3 + fsigmoid(zi) * ftanh_(zg);
            hl3 = fsigmoid(zo) * ftanh_(c3);

            *(float4*)(hw + lane * H_K_STRIDE + warp4) = make_float4(hl0, hl1, hl2, hl3);
            __syncwarp();
            cur ^= 1;
        }
    }

    // ---- output head: out[b] = sum_j h[b][j] * W_out[j] + b_out[0] ----
    const float wo = W_out[lane];
    float v0 = hl0 * wo, v1 = hl1 * wo, v2 = hl2 * wo, v3 = hl3 * wo;
#pragma unroll
    for (int off = 16; off; off >>= 1) {
        v0 += __shfl_xor_sync(0xffffffffu, v0, off);
        v1 += __shfl_xor_sync(0xffffffffu, v1, off);
        v2 += __shfl_xor_sync(0xffffffffu, v2, off);
        v3 += __shfl_xor_sync(0xffffffffu, v3, off);
    }
    if (lane == 0) {
        const float bout = b_out[0];
        const int bb = blockIdx.x * BATCH_PER_CTA + warp * NB;
        out[bb + 0] = v0 + bout;
        out[bb + 1] = v1 + bout;
        out[bb + 2] = v2 + bout;
        out[bb + 3] = v3 + bout;
    }
}

extern "C" void kernel_launch(void* const* d_in, const int* in_sizes, int n_in,
                              void* d_out, int out_size)
{
    const float* x     = (const float*)d_in[0];
    const float* W_ih  = (const float*)d_in[1];
    const float* W_hh  = (const float*)d_in[2];
    const float* b_ih  = (const float*)d_in[3];
    const float* b_hh  = (const float*)d_in[4];
    const float* W_out = (const float*)d_in[5];
    const float* b_out = (const float*)d_in[6];
    float* out = (float*)d_out;

    lstm_kernel<<<B_TOT / BATCH_PER_CTA, WARPS_PER_CTA * 32>>>(
        x, W_ih, W_hh, b_ih, b_hh, W_out, b_out, out);
}

// round 2
// speedup vs baseline: 1.2362x; 1.2362x over previous
#include <cuda_runtime.h>
#include <cstdint>

// LSTM B=4096 T=256 I=8 H=32 O=1.
// Warp = 4 batches; lane j = hidden unit j (all 4 gates).
// f32x2 lanes hold BATCH pairs {b0,b1},{b2,b3}; W_hh held in 128 registers as
// duplicated pairs {w,w} -> recurrent k-iter = 1 broadcast LDS.128 + 8 FFMA2,
// zero packs, zero weight loads. W_ih pre-duplicated in smem (8 iters/step).
// Activations via MUFU tanh.approx; sigmoid(z)=0.5*tanh(z/2)+0.5.

#define B_TOT 4096
#define T_TOT 256
#define I_SZ 8
#define H_SZ 32
#define WARPS_PER_CTA 4
#define NB 4
#define BATCH_PER_CTA 16
#define CHUNK 16

#define X_T_STRIDE 132      // floats; 528B, 16B-aligned
#define X_I_STRIDE 16       // floats; 64B

typedef unsigned long long u64;

__device__ __forceinline__ u64 pack2(float a, float b) {
    u64 r; asm("mov.b64 %0,{%1,%2};" : "=l"(r) : "f"(a), "f"(b)); return r;
}
__device__ __forceinline__ void unpack2(u64 v, float& a, float& b) {
    asm("mov.b64 {%0,%1},%2;" : "=f"(a), "=f"(b) : "l"(v));
}
__device__ __forceinline__ u64 fma2(u64 a, u64 b, u64 c) {
    u64 d; asm("fma.rn.f32x2 %0,%1,%2,%3;" : "=l"(d) : "l"(a), "l"(b), "l"(c)); return d;
}
__device__ __forceinline__ float tanhap(float x) {
    float y; asm("tanh.approx.f32 %0,%1;" : "=f"(y) : "f"(x)); return y;
}
__device__ __forceinline__ float sigap(float z) {
    return fmaf(0.5f, tanhap(0.5f * z), 0.5f);
}

__global__ void __launch_bounds__(128, 2)
lstm_kernel(const float* __restrict__ x,
            const float* __restrict__ W_ih,
            const float* __restrict__ W_hh,
            const float* __restrict__ b_ih,
            const float* __restrict__ b_hh,
            const float* __restrict__ W_out,
            const float* __restrict__ b_out,
            float* __restrict__ out)
{
    __shared__ __align__(16) float wh_t[32 * 33];                 // transpose scratch (reused per gate)
    __shared__ __align__(16) u64   wi_d[I_SZ * 4 * 32];           // [i][g][j] duplicated pairs
    __shared__ __align__(16) float x_sm[CHUNK * X_T_STRIDE];      // [t][i][b]
    __shared__ __align__(16) float h_sm[WARPS_PER_CTA * 2 * 32 * 4];

    const int tid   = threadIdx.x;
    const int lane  = tid & 31;
    const int warp  = tid >> 5;
    const int warp4 = warp * NB;

    // ---- W_hh into registers, duplicated {w,w} per (gate, k) ----
    u64 wd[4][32];
#pragma unroll
    for (int g = 0; g < 4; ++g) {
        __syncthreads();
        for (int idx = tid; idx < 1024; idx += 128) {
            int j = idx >> 5, k = idx & 31;           // W_hh row = g*32+j, col = k
            wh_t[k * 33 + j] = W_hh[g * 1024 + idx];
        }
        __syncthreads();
#pragma unroll
        for (int k = 0; k < 32; ++k) {
            float w = wh_t[k * 33 + lane];
            wd[g][k] = pack2(w, w);
        }
    }

    // ---- W_ih duplicated pairs into smem: wi_d[i*128 + g*32 + j] = {w,w} ----
    for (int idx = tid; idx < 1024; idx += 128) {
        int i = idx >> 7, g = (idx >> 5) & 3, j = idx & 31;
        float w = W_ih[(g * 32 + j) * I_SZ + i];
        wi_d[idx] = pack2(w, w);
    }

    // ---- zero h buffers ----
    for (int idx = tid; idx < WARPS_PER_CTA * 2 * 32 * 4; idx += 128) h_sm[idx] = 0.0f;

    // ---- bias dups (b_ih + b_hh per gate, lane j) ----
    const float bi = b_ih[0 * 32 + lane] + b_hh[0 * 32 + lane];
    const float bf = b_ih[1 * 32 + lane] + b_hh[1 * 32 + lane];
    const float bg = b_ih[2 * 32 + lane] + b_hh[2 * 32 + lane];
    const float bo = b_ih[3 * 32 + lane] + b_hh[3 * 32 + lane];
    const u64 bdi = pack2(bi, bi), bdf = pack2(bf, bf);
    const u64 bdg = pack2(bg, bg), bdo = pack2(bo, bo);

    float c0 = 0.f, c1 = 0.f, c2 = 0.f, c3 = 0.f;
    float h0 = 0.f, h1 = 0.f, h2 = 0.f, h3 = 0.f;

    float* h_warp = h_sm + warp * 256;   // [2][32][4] floats, per-warp private
    int cur = 0;

    const size_t xbase = (size_t)blockIdx.x * BATCH_PER_CTA * T_TOT * I_SZ;

#pragma unroll 1
    for (int tc = 0; tc < T_TOT / CHUNK; ++tc) {
        __syncthreads();     // everyone done with previous x chunk
        // ---- stage x chunk: x_sm[t][i][b] ----
#pragma unroll
        for (int q = 0; q < 4; ++q) {
            int b  = q * 4 + warp;                 // 0..15
            int t  = lane >> 1;                    // 0..15
            int i0 = (lane & 1) * 4;               // 0 or 4
            const float4 v = *(const float4*)(x + xbase
                              + ((size_t)b * T_TOT + tc * CHUNK + t) * I_SZ + i0);
            float* dst = x_sm + t * X_T_STRIDE + i0 * X_I_STRIDE + b;
            dst[0 * X_I_STRIDE] = v.x;
            dst[1 * X_I_STRIDE] = v.y;
            dst[2 * X_I_STRIDE] = v.z;
            dst[3 * X_I_STRIDE] = v.w;
        }
        __syncthreads();

#pragma unroll 1
        for (int s = 0; s < CHUNK; ++s) {
            const float* hr = h_warp + cur * 128;
            float*       hw = h_warp + (cur ^ 1) * 128;

            u64 zi01 = bdi, zi23 = bdi;
            u64 zf01 = bdf, zf23 = bdf;
            u64 zg01 = bdg, zg23 = bdg;
            u64 zo01 = bdo, zo23 = bdo;

            // ---- input projection (x batch-pairs broadcast, dup weights from smem) ----
#pragma unroll
            for (int i = 0; i < I_SZ; ++i) {
                const ulonglong2 xv = *(const ulonglong2*)(x_sm + s * X_T_STRIDE + i * X_I_STRIDE + warp4);
                const u64 w0 = wi_d[i * 128 + 0 * 32 + lane];
                const u64 w1 = wi_d[i * 128 + 1 * 32 + lane];
                const u64 w2 = wi_d[i * 128 + 2 * 32 + lane];
                const u64 w3 = wi_d[i * 128 + 3 * 32 + lane];
                zi01 = fma2(xv.x, w0, zi01); zi23 = fma2(xv.y, w0, zi23);
                zf01 = fma2(xv.x, w1, zf01); zf23 = fma2(xv.y, w1, zf23);
                zg01 = fma2(xv.x, w2, zg01); zg23 = fma2(xv.y, w2, zg23);
                zo01 = fma2(xv.x, w3, zo01); zo23 = fma2(xv.y, w3, zo23);
            }

            // ---- recurrent projection: weights from registers, h broadcast ----
#pragma unroll
            for (int k = 0; k < H_SZ; ++k) {
                const ulonglong2 hv = *(const ulonglong2*)(hr + k * 4);
                zi01 = fma2(hv.x, wd[0][k], zi01); zi23 = fma2(hv.y, wd[0][k], zi23);
                zf01 = fma2(hv.x, wd[1][k], zf01); zf23 = fma2(hv.y, wd[1][k], zf23);
                zg01 = fma2(hv.x, wd[2][k], zg01); zg23 = fma2(hv.y, wd[2][k], zg23);
                zo01 = fma2(hv.x, wd[3][k], zo01); zo23 = fma2(hv.y, wd[3][k], zo23);
            }

            // ---- gates + state update ----
            float zi0, zi1, zi2, zi3, zf0, zf1, zf2, zf3;
            float zg0, zg1, zg2, zg3, zo0, zo1, zo2, zo3;
            unpack2(zi01, zi0, zi1); unpack2(zi23, zi2, zi3);
            unpack2(zf01, zf0, zf1); unpack2(zf23, zf2, zf3);
            unpack2(zg01, zg0, zg1); unpack2(zg23, zg2, zg3);
            unpack2(zo01, zo0, zo1); unpack2(zo23, zo2, zo3);

            c0 = fmaf(sigap(zf0), c0, sigap(zi0) * tanhap(zg0)); h0 = sigap(zo0) * tanhap(c0);
            c1 = fmaf(sigap(zf1), c1, sigap(zi1) * tanhap(zg1)); h1 = sigap(zo1) * tanhap(c1);
            c2 = fmaf(sigap(zf2), c2, sigap(zi2) * tanhap(zg2)); h2 = sigap(zo2) * tanhap(c2);
            c3 = fmaf(sigap(zf3), c3, sigap(zi3) * tanhap(zg3)); h3 = sigap(zo3) * tanhap(c3);

            *(float4*)(hw + lane * 4) = make_float4(h0, h1, h2, h3);
            __syncwarp();
            cur ^= 1;
        }
    }

    // ---- output head: out[b] = sum_j h[b][j]*W_out[j] + b_out ----
    const float wo = W_out[lane];
    float v0 = h0 * wo, v1 = h1 * wo, v2 = h2 * wo, v3 = h3 * wo;
#pragma unroll
    for (int off = 16; off; off >>= 1) {
        v0 += __shfl_xor_sync(0xffffffffu, v0, off);
        v1 += __shfl_xor_sync(0xffffffffu, v1, off);
        v2 += __shfl_xor_sync(0xffffffffu, v2, off);
        v3 += __shfl_xor_sync(0xffffffffu, v3, off);
    }
    if (lane == 0) {
        const float bout = b_out[0];
        const int bb = blockIdx.x * BATCH_PER_CTA + warp * NB;
        out[bb + 0] = v0 + bout;
        out[bb + 1] = v1 + bout;
        out[bb + 2] = v2 + bout;
        out[bb + 3] = v3 + bout;
    }
}

extern "C" void kernel_launch(void* const* d_in, const int* in_sizes, int n_in,
                              void* d_out, int out_size)
{
    const float* x     = (const float*)d_in[0];
    const float* W_ih  = (const float*)d_in[1];
    const float* W_hh  = (const float*)d_in[2];
    const float* b_ih  = (const float*)d_in[3];
    const float* b_hh  = (const float*)d_in[4];
    const float* W_out = (const float*)d_in[5];
    const float* b_out = (const float*)d_in[6];
    float* out = (float*)d_out;

    lstm_kernel<<<B_TOT / BATCH_PER_CTA, WARPS_PER_CTA * 32>>>(
        x, W_ih, W_hh, b_ih, b_hh, W_out, b_out, out);
}